// round 1
// baseline (speedup 1.0000x reference)
#include <cuda_runtime.h>
#include <cuda_bf16.h>
#include <cstdint>

#define BSZ 32
#define LEN 8192
#define NPF 256          // output feature dim
#define SEGLEN 512
#define INTMX 0x7fffffff

// Scratch (no allocations allowed): cumsum + per-row start/valid
__device__ int g_cum[BSZ * LEN];
__device__ int g_start[BSZ];
__device__ int g_valid[BSZ];

// ---------------------------------------------------------------------------
// Kernel A: per-row inclusive cumsum of mask + first-valid index.
// One block per row, 1024 threads x 8 elements.
// ---------------------------------------------------------------------------
__global__ void scan_kernel(const int* __restrict__ mask) {
    const int b = blockIdx.x;
    const int tid = threadIdx.x;
    const int* m = mask + (size_t)b * LEN;

    int4 ld0 = ((const int4*)m)[tid * 2 + 0];
    int4 ld1 = ((const int4*)m)[tid * 2 + 1];
    int v[8] = {ld0.x, ld0.y, ld0.z, ld0.w, ld1.x, ld1.y, ld1.z, ld1.w};

    const int base = tid * 8;
    int fv = INTMX;
#pragma unroll
    for (int t = 7; t >= 0; --t)
        if (v[t]) fv = base + t;

#pragma unroll
    for (int t = 1; t < 8; ++t) v[t] += v[t - 1];
    const int tot = v[7];

    const int lane = tid & 31, wid = tid >> 5;
    int x = tot;
#pragma unroll
    for (int o = 1; o < 32; o <<= 1) {
        int y = __shfl_up_sync(0xffffffffu, x, o);
        if (lane >= o) x += y;
    }

    __shared__ int wsum[32];
    __shared__ int wmin[32];
    if (lane == 31) wsum[wid] = x;
#pragma unroll
    for (int o = 16; o; o >>= 1) fv = min(fv, __shfl_xor_sync(0xffffffffu, fv, o));
    if (lane == 0) wmin[wid] = fv;
    __syncthreads();

    if (wid == 0) {
        int t = wsum[lane];
#pragma unroll
        for (int o = 1; o < 32; o <<= 1) {
            int y = __shfl_up_sync(0xffffffffu, t, o);
            if (lane >= o) t += y;
        }
        wsum[lane] = t;
        int mn = wmin[lane];
#pragma unroll
        for (int o = 16; o; o >>= 1) mn = min(mn, __shfl_xor_sync(0xffffffffu, mn, o));
        if (lane == 0) {
            g_start[b] = (mn == INTMX) ? 0 : mn;
            g_valid[b] = (mn != INTMX) ? 1 : 0;
        }
    }
    __syncthreads();

    const int offset = (x - tot) + (wid ? wsum[wid - 1] : 0);
    int* c = g_cum + (size_t)b * LEN;
    int4 o0 = make_int4(v[0] + offset, v[1] + offset, v[2] + offset, v[3] + offset);
    int4 o1 = make_int4(v[4] + offset, v[5] + offset, v[6] + offset, v[7] + offset);
    ((int4*)c)[tid * 2 + 0] = o0;
    ((int4*)c)[tid * 2 + 1] = o1;
}

// ---------------------------------------------------------------------------
// Kernel B: main embedding. Block = (b, segment). 256 threads:
//   j = tid & 63   -> feature pairs {2j, 2j+1}  (float4 per i)
//   chunk = tid>>6 -> 128-element i sub-range (exact reseed at chunk start)
// Along i: conditional rotation by delta when mask==1.
// ---------------------------------------------------------------------------
__global__ void __launch_bounds__(256) embed_kernel(const int* __restrict__ mask,
                                                    float* __restrict__ out) {
    const int b = blockIdx.y;
    const int seg = blockIdx.x;
    if (!g_valid[b]) return;
    const int start = g_start[b];
    const int i0 = start + seg * SEGLEN;
    if (i0 >= LEN) return;
    const int i1 = min(i0 + SEGLEN, LEN);
    const int tid = threadIdx.x;

    __shared__ int sm[SEGLEN];
    const int* mrow = mask + (size_t)b * LEN;
    for (int t = tid; t < i1 - i0; t += 256) sm[t] = mrow[i0 + t];
    __syncthreads();

    const int* cum = g_cum + (size_t)b * LEN;
    const int c_prev = (i0 > 0) ? cum[i0 - 1] : 0;
    const int n = cum[i1 - 1] - c_prev;
    const float base = 6.283185307179586f / ((float)n + 1e-6f);

    const int j = tid & 63;
    const int chunk = tid >> 6;
    const int ia = i0 + chunk * 128;
    if (ia >= i1) return;
    const int ib = min(ia + 128, i1);

    // delta for the two feature pairs 2j and 2j+1
    const float K2 = 0.10381025296523007f;  // log2(10000)/128
    const float p0 = (float)(2 * j);
    const float p1 = (float)(2 * j + 1);
    const float d0 = base * exp2f(-p0 * K2);
    const float d1 = base * exp2f(-p1 * K2);

    // exact reseed: count strictly before ia within this segment
    const int m0 = ((ia > 0) ? cum[ia - 1] : 0) - c_prev;
    float s0, c0, s1, c1, sd0, cd0, sd1, cd1;
    __sincosf((float)m0 * d0, &s0, &c0);
    __sincosf((float)m0 * d1, &s1, &c1);
    __sincosf(d0, &sd0, &cd0);
    __sincosf(d1, &sd1, &cd1);

    float4* op = (float4*)(out + (size_t)(b * LEN + ia) * NPF) + j;
    for (int i = ia; i < ib; ++i, op += NPF / 4) {
        if (sm[i - i0]) {  // uniform per warp: all lanes share i
            float ns0 = fmaf(s0, cd0, c0 * sd0);
            float nc0 = fmaf(c0, cd0, -s0 * sd0);
            float ns1 = fmaf(s1, cd1, c1 * sd1);
            float nc1 = fmaf(c1, cd1, -s1 * sd1);
            s0 = ns0; c0 = nc0; s1 = ns1; c1 = nc1;
        }
        *op = make_float4(s0, c0, s1, c1);
    }
}

// ---------------------------------------------------------------------------
// Kernel C: fill prefix (i < start) and fully-invalid rows with (0,1,0,1,...).
// One thread per (b, i); almost all threads exit immediately for random masks.
// ---------------------------------------------------------------------------
__global__ void fill_kernel(float* __restrict__ out) {
    const int gid = blockIdx.x * 256 + threadIdx.x;  // 0 .. 32*8192-1
    const int b = gid >> 13;
    const int i = gid & (LEN - 1);
    if (g_valid[b] && i >= g_start[b]) return;
    const float4 pat = make_float4(0.0f, 1.0f, 0.0f, 1.0f);
    float4* o = (float4*)(out + (size_t)gid * NPF);
#pragma unroll
    for (int t = 0; t < NPF / 4; ++t) o[t] = pat;
}

extern "C" void kernel_launch(void* const* d_in, const int* in_sizes, int n_in,
                              void* d_out, int out_size) {
    (void)in_sizes; (void)n_in; (void)out_size;
    const int* mask = (const int*)d_in[1];   // inputs: x (unused), mask
    float* out = (float*)d_out;

    scan_kernel<<<BSZ, 1024>>>(mask);
    embed_kernel<<<dim3(16, BSZ), 256>>>(mask, out);
    fill_kernel<<<(BSZ * LEN) / 256, 256>>>(out);
}

// round 2
// speedup vs baseline: 1.1022x; 1.1022x over previous
#include <cuda_runtime.h>
#include <cuda_bf16.h>
#include <cstdint>

#define BSZ 32
#define LEN 8192
#define NPF 256          // output feature dim
#define SEGLEN 512
#define INTMX 0x7fffffff

// Tiny scratch: per-row first-valid index + validity flag
__device__ int g_start[BSZ];
__device__ int g_valid[BSZ];

// ---------------------------------------------------------------------------
// Kernel A: per-row first-valid index only. One block per row, 1024 threads.
// Reads 1MB, writes 256B. No cumsum array anymore.
// ---------------------------------------------------------------------------
__global__ void start_kernel(const int* __restrict__ mask) {
    const int b = blockIdx.x;
    const int tid = threadIdx.x;
    const int* m = mask + (size_t)b * LEN;

    int4 a = ((const int4*)m)[tid * 2 + 0];
    int4 c = ((const int4*)m)[tid * 2 + 1];
    int v[8] = {a.x, a.y, a.z, a.w, c.x, c.y, c.z, c.w};

    const int base = tid * 8;
    int fv = INTMX;
#pragma unroll
    for (int t = 7; t >= 0; --t)
        if (v[t]) fv = base + t;

    const int lane = tid & 31, wid = tid >> 5;
#pragma unroll
    for (int o = 16; o; o >>= 1) fv = min(fv, __shfl_xor_sync(0xffffffffu, fv, o));

    __shared__ int wmin[32];
    if (lane == 0) wmin[wid] = fv;
    __syncthreads();
    if (wid == 0) {
        int mn = wmin[lane];
#pragma unroll
        for (int o = 16; o; o >>= 1) mn = min(mn, __shfl_xor_sync(0xffffffffu, mn, o));
        if (lane == 0) {
            g_start[b] = (mn == INTMX) ? 0 : mn;
            g_valid[b] = (mn != INTMX) ? 1 : 0;
        }
    }
}

// ---------------------------------------------------------------------------
// Kernel B: embedding + fill, fused. Grid (17, BSZ), 256 threads.
//   seg 0..15 : segment [start+seg*512, +512) — conditional-rotation stores
//   seg 16    : prefix fill [0, start) with (0,1,0,1,...), or whole row if
//               the row has no valid position (always empty region otherwise,
//               since start + 16*512 >= LEN).
// Per-chunk seed counts come from a local reduction of the smem mask tile —
// no global cumsum needed.
// ---------------------------------------------------------------------------
__global__ void __launch_bounds__(256) embed_kernel(const int* __restrict__ mask,
                                                    float* __restrict__ out) {
    const int b = blockIdx.y;
    const int seg = blockIdx.x;
    const int tid = threadIdx.x;
    const int valid = g_valid[b];
    const int start = g_start[b];

    if (seg == 16) {
        // fill [0, fill_end) with interleaved sin(0)=0 / cos(0)=1 pattern
        const int fill_end = valid ? start : LEN;
        if (fill_end == 0) return;
        const float4 pat = make_float4(0.0f, 1.0f, 0.0f, 1.0f);
        float4* o = (float4*)(out + (size_t)b * LEN * NPF);
        const int total = fill_end * (NPF / 4);
        for (int t = tid; t < total; t += 256) o[t] = pat;
        return;
    }

    if (!valid) return;
    const int i0 = start + seg * SEGLEN;
    if (i0 >= LEN) return;
    const int i1 = min(i0 + SEGLEN, LEN);
    const int nseg = i1 - i0;

    __shared__ int sm[SEGLEN];
    __shared__ int part[4];
    const int* mrow = mask + (size_t)b * LEN;
#pragma unroll
    for (int t = tid; t < SEGLEN; t += 256) sm[t] = (t < nseg) ? mrow[i0 + t] : 0;
    __syncthreads();

    // per-128-chunk mask counts: warp w (w<4) reduces sm[w*128 .. w*128+127]
    if (tid < 128) {
        const int w = tid >> 5, lane = tid & 31;
        int s = sm[w * 128 + lane * 4 + 0] + sm[w * 128 + lane * 4 + 1] +
                sm[w * 128 + lane * 4 + 2] + sm[w * 128 + lane * 4 + 3];
#pragma unroll
        for (int o = 16; o; o >>= 1) s += __shfl_xor_sync(0xffffffffu, s, o);
        if (lane == 0) part[w] = s;
    }
    __syncthreads();

    const int chunk = tid >> 6;
    const int j = tid & 63;
    const int ia = i0 + chunk * 128;
    if (ia >= i1) return;
    const int ib = min(ia + 128, i1);

    int m0 = 0;
#pragma unroll
    for (int w = 0; w < 4; ++w) if (w < chunk) m0 += part[w];
    const int n = part[0] + part[1] + part[2] + part[3];
    const float base = 6.283185307179586f / ((float)n + 1e-6f);

    // per-thread rotation deltas for feature pairs 2j, 2j+1
    const float K2 = 0.10381025296523007f;  // log2(10000)/128
    const float d0 = base * exp2f(-(float)(2 * j) * K2);
    const float d1 = base * exp2f(-(float)(2 * j + 1) * K2);

    float s0, c0, s1, c1, sd0, cd0, sd1, cd1;
    __sincosf((float)m0 * d0, &s0, &c0);
    __sincosf((float)m0 * d1, &s1, &c1);
    __sincosf(d0, &sd0, &cd0);
    __sincosf(d1, &sd1, &cd1);

    float4* op = (float4*)(out + (size_t)(b * LEN + ia) * NPF) + j;
    const int* smc = sm + (ia - i0);
    const int cnt = ib - ia;
#pragma unroll 4
    for (int i = 0; i < cnt; ++i, op += NPF / 4) {
        if (smc[i]) {  // warp-uniform: all lanes in a warp share chunk/i
            float ns0 = fmaf(s0, cd0, c0 * sd0);
            float nc0 = fmaf(c0, cd0, -s0 * sd0);
            float ns1 = fmaf(s1, cd1, c1 * sd1);
            float nc1 = fmaf(c1, cd1, -s1 * sd1);
            s0 = ns0; c0 = nc0; s1 = ns1; c1 = nc1;
        }
        *op = make_float4(s0, c0, s1, c1);
    }
}

extern "C" void kernel_launch(void* const* d_in, const int* in_sizes, int n_in,
                              void* d_out, int out_size) {
    (void)in_sizes; (void)n_in; (void)out_size;
    const int* mask = (const int*)d_in[1];   // inputs: x (unused), mask
    float* out = (float*)d_out;

    start_kernel<<<BSZ, 1024>>>(mask);
    embed_kernel<<<dim3(17, BSZ), 256>>>(mask, out);
}